// round 2
// baseline (speedup 1.0000x reference)
#include <cuda_runtime.h>

#define MUL     128
#define G_NUM   32
#define N_ROWS  2048
#define R_TILE  16
#define NCHUNK  6
#define XPAD    129     // 128 + 1 pad to avoid smem bank conflicts on row stride

__device__ int g_off[G_NUM + 1];

__global__ void scan_repeats(const int* __restrict__ rep) {
    if (threadIdx.x == 0) {
        int s = 0;
        for (int g = 0; g < G_NUM; ++g) { g_off[g] = s; s += rep[g]; }
        g_off[G_NUM] = s;
    }
}

// Block: (group g, row-chunk ck, out-tile ot of 64 channels).
// Computes y[n, o, i] = alpha * sum_m x[n, m, i] * w[g, m, o]
// for rows of group g in this chunk, o in [ot*64, ot*64+64), all i < D.
template <int D>
__global__ __launch_bounds__(256)
void ilin_kernel(const float* __restrict__ x, const float* __restrict__ w,
                 float* __restrict__ y, int woff)
{
    extern __shared__ float smem[];
    float* W_s = smem;              // 128 (m) x 64 (o) = 8192 floats = 32 KB
    float* x_s = smem + 8192;       // D * 16 rows * XPAD floats (transposed)

    const int g   = blockIdx.x;
    const int ck  = blockIdx.y;
    const int ot  = blockIdx.z;
    const int tid = threadIdx.x;
    const int oq  = tid & 15;       // out-quad: o = ot*64 + oq*4 + j
    const int cg  = tid >> 4;       // row within tile (0..15)

    const int row_begin = g_off[g];
    const int row_end   = g_off[g + 1];
    if (row_begin + ck * R_TILE >= row_end) return;   // block-uniform

    // ---- load W tile into smem (coalesced float4) ----
    {
        const float* wg = w + (size_t)g * (3 * MUL * MUL) + woff + ot * 64;
        float4* Ws4 = (float4*)W_s;
        #pragma unroll
        for (int t = 0; t < 8; ++t) {
            int idx = tid + t * 256;            // 0..2047
            int m = idx >> 4, q = idx & 15;
            Ws4[idx] = *(const float4*)(wg + m * MUL + q * 4);
        }
    }

    for (int r0 = row_begin + ck * R_TILE; r0 < row_end; r0 += NCHUNK * R_TILE) {
        const int nr = min(R_TILE, row_end - r0);
        __syncthreads();    // prior compute done (and W_s ready on 1st iter)

        // ---- stage x rows transposed: x_s[(i*16 + r)*XPAD + m] ----
        {
            const float* xg = x + (size_t)r0 * MUL * D;
            const int total = nr * MUL * D;
            for (int idx = tid; idx < total; idx += 256) {
                int r   = idx / (MUL * D);
                int rem = idx - r * (MUL * D);
                int m   = rem / D;
                int i   = rem - m * D;
                x_s[(i * R_TILE + r) * XPAD + m] = xg[idx];
            }
        }
        __syncthreads();

        if (cg < nr) {
            float acc[D][4];
            #pragma unroll
            for (int k = 0; k < D; ++k)
                acc[k][0] = acc[k][1] = acc[k][2] = acc[k][3] = 0.f;

            const float4* Ws4 = (const float4*)W_s;
            #pragma unroll 4
            for (int m = 0; m < MUL; ++m) {
                float4 w4 = Ws4[m * 16 + oq];
                #pragma unroll
                for (int k = 0; k < D; ++k) {
                    float xv = x_s[(k * R_TILE + cg) * XPAD + m];
                    acc[k][0] += xv * w4.x;
                    acc[k][1] += xv * w4.y;
                    acc[k][2] += xv * w4.z;
                    acc[k][3] += xv * w4.w;
                }
            }

            const float alpha = 0.015625f;   // 1/sqrt(32*128) = 1/64 exactly
            float* yr = y + ((size_t)(r0 + cg) * MUL + ot * 64 + oq * 4) * D;
            #pragma unroll
            for (int j = 0; j < 4; ++j)
                #pragma unroll
                for (int k = 0; k < D; ++k)
                    yr[j * D + k] = acc[k][j] * alpha;
        }
    }
}

extern "C" void kernel_launch(void* const* d_in, const int* in_sizes, int n_in,
                              void* d_out, int out_size)
{
    const float* x0  = (const float*)d_in[0];   // (N, 128, 1)
    const float* x1  = (const float*)d_in[1];   // (N, 128, 3)
    const float* x2  = (const float*)d_in[2];   // (N, 128, 5)
    const float* w   = (const float*)d_in[3];   // (32, 3*128*128)
    const int*   rep = (const int*)d_in[4];     // (32,)
    float* y = (float*)d_out;                   // concat(y0, y1, y2)

    scan_repeats<<<1, 32>>>(rep);

    const size_t sm1 = (8192 + 1 * R_TILE * XPAD) * sizeof(float);
    const size_t sm3 = (8192 + 3 * R_TILE * XPAD) * sizeof(float);
    const size_t sm5 = (8192 + 5 * R_TILE * XPAD) * sizeof(float);
    cudaFuncSetAttribute(ilin_kernel<1>, cudaFuncAttributeMaxDynamicSharedMemorySize, (int)sm1);
    cudaFuncSetAttribute(ilin_kernel<3>, cudaFuncAttributeMaxDynamicSharedMemorySize, (int)sm3);
    cudaFuncSetAttribute(ilin_kernel<5>, cudaFuncAttributeMaxDynamicSharedMemorySize, (int)sm5);

    dim3 grid(G_NUM, NCHUNK, 2);
    ilin_kernel<1><<<grid, 256, sm1>>>(x0, w, y,                              0);
    ilin_kernel<3><<<grid, 256, sm3>>>(x1, w, y + (size_t)N_ROWS * MUL * 1, 16384);
    ilin_kernel<5><<<grid, 256, sm5>>>(x2, w, y + (size_t)N_ROWS * MUL * 4, 32768);
}

// round 5
// speedup vs baseline: 1.8943x; 1.8943x over previous
#include <cuda_runtime.h>
#include <cuda_bf16.h>
#include <cstdint>

#define G_NUM   32
#define N_ROWS  2048
#define APAD    136                 // smem row stride in bf16 elems (272B)
#define A_HI_OFF 0
#define A_LO_OFF (128 * APAD)
#define B_HI_OFF (2 * 128 * APAD)
#define B_LO_OFF (3 * 128 * APAD)
#define SMEM_BYTES (4 * 128 * APAD * 2)   // 139264

__device__ int g_off2[G_NUM + 1];

__global__ void scan_repeats(const int* __restrict__ rep) {
    if (threadIdx.x == 0) {
        int s = 0;
        for (int g = 0; g < G_NUM; ++g) { g_off2[g] = s; s += rep[g]; }
        g_off2[G_NUM] = s;
    }
}

static __device__ __forceinline__ uint32_t smem_u32(const void* p) {
    uint32_t a;
    asm("{ .reg .u64 t; cvta.to.shared.u64 t, %1; cvt.u32.u64 %0, t; }" : "=r"(a) : "l"(p));
    return a;
}
static __device__ __forceinline__ void ldmx4(uint32_t* r, uint32_t addr) {
    asm volatile("ldmatrix.sync.aligned.m8n8.x4.shared.b16 {%0,%1,%2,%3}, [%4];"
                 : "=r"(r[0]), "=r"(r[1]), "=r"(r[2]), "=r"(r[3]) : "r"(addr));
}
static __device__ __forceinline__ void mma16816(float* c, const uint32_t* a, const uint32_t* b) {
    asm volatile(
        "mma.sync.aligned.m16n8k16.row.col.f32.bf16.bf16.f32 "
        "{%0,%1,%2,%3}, {%4,%5,%6,%7}, {%8,%9}, {%0,%1,%2,%3};"
        : "+f"(c[0]), "+f"(c[1]), "+f"(c[2]), "+f"(c[3])
        : "r"(a[0]), "r"(a[1]), "r"(a[2]), "r"(a[3]), "r"(b[0]), "r"(b[1]));
}
static __device__ __forceinline__ uint32_t pack_split(float v0, float v1, uint32_t& lo_pack) {
    __nv_bfloat16 h0 = __float2bfloat16(v0);
    __nv_bfloat16 h1 = __float2bfloat16(v1);
    __nv_bfloat16 l0 = __float2bfloat16(v0 - __bfloat162float(h0));
    __nv_bfloat16 l1 = __float2bfloat16(v1 - __bfloat162float(h1));
    __nv_bfloat162 hp(h0, h1), lp(l0, l1);
    lo_pack = *reinterpret_cast<uint32_t*>(&lp);
    return *reinterpret_cast<uint32_t*>(&hp);
}

// One 128-row M-tile of group g for irrep dim D.
// Y[mi, o] = sum_m X[mi, m] * (alpha * W[m, o]),  mi = local_row*D + i.
template <int D>
__device__ __forceinline__ void run_tile(__nv_bfloat16* sm, uint32_t smem_base,
                                         const float* __restrict__ x,
                                         const float* __restrict__ wg,
                                         float* __restrict__ y,
                                         int g, int t)
{
    const int tid  = threadIdx.x;
    const int wid  = tid >> 5;
    const int lane = tid & 31;

    const int row_begin = g_off2[g];
    const int rows = g_off2[g + 1] - row_begin;
    const int Mg   = rows * D;
    const int mi0  = t * 128;
    if (mi0 >= Mg) return;
    const int valid = min(128, Mg - mi0);

    // ---- stage A: X tile -> bf16 hi/lo, [mi_l][k], packed u32 stores ----
    #pragma unroll 2
    for (int e = tid; e < 128 * 64; e += 256) {
        const int mi_l = e >> 6;
        const int k2   = e & 63;
        float v0 = 0.f, v1 = 0.f;
        if (mi_l < valid) {
            const int mi = mi0 + mi_l;
            const int r  = mi / D;
            const int i  = mi - r * D;
            const float* xr = x + ((size_t)(row_begin + r) * 128) * D + i;
            v0 = xr[(2 * k2) * D];
            v1 = xr[(2 * k2 + 1) * D];
        }
        uint32_t lp, hp = pack_split(v0, v1, lp);
        *reinterpret_cast<uint32_t*>(sm + A_HI_OFF + mi_l * APAD + 2 * k2) = hp;
        *reinterpret_cast<uint32_t*>(sm + A_LO_OFF + mi_l * APAD + 2 * k2) = lp;
    }

    // ---- stage B: W^T tile (row=o, col=m) -> bf16 hi/lo, alpha folded ----
    #pragma unroll 2
    for (int e = tid; e < 64 * 128; e += 256) {
        const int m2 = e >> 7;
        const int o  = e & 127;
        const float v0 = wg[(2 * m2) * 128 + o] * 0.015625f;
        const float v1 = wg[(2 * m2 + 1) * 128 + o] * 0.015625f;
        uint32_t lp, hp = pack_split(v0, v1, lp);
        *reinterpret_cast<uint32_t*>(sm + B_HI_OFF + o * APAD + 2 * m2) = hp;
        *reinterpret_cast<uint32_t*>(sm + B_LO_OFF + o * APAD + 2 * m2) = lp;
    }
    __syncthreads();

    // ---- warp tiling: 4x2 warps, each M32 x N64 ----
    const int mbase = (wid >> 1) * 32;
    const int nbase = (wid & 1) * 64;

    float acc[2][8][4];
    #pragma unroll
    for (int a = 0; a < 2; ++a)
        #pragma unroll
        for (int b = 0; b < 8; ++b)
            #pragma unroll
            for (int c = 0; c < 4; ++c) acc[a][b][c] = 0.f;

    // per-lane ldmatrix base addresses
    const uint32_t a_row  = mbase + (lane & 7) + ((lane >> 3) & 1) * 8;
    const uint32_t a_colh = (lane >> 4) * 8;
    const uint32_t b_row  = nbase + (lane & 7) + ((lane >> 4) & 1) * 8;
    const uint32_t b_colh = ((lane >> 3) & 1) * 8;
    const uint32_t aHi = smem_base + (A_HI_OFF + a_row * APAD + a_colh) * 2;
    const uint32_t aLo = smem_base + (A_LO_OFF + a_row * APAD + a_colh) * 2;
    const uint32_t bHi = smem_base + (B_HI_OFF + b_row * APAD + b_colh) * 2;
    const uint32_t bLo = smem_base + (B_LO_OFF + b_row * APAD + b_colh) * 2;

    #pragma unroll
    for (int k = 0; k < 8; ++k) {
        const uint32_t kof = k * 32;   // k16 step = 32 bytes
        uint32_t ah[2][4], al[2][4];
        ldmx4(ah[0], aHi + kof);
        ldmx4(ah[1], aHi + 16 * APAD * 2 + kof);
        ldmx4(al[0], aLo + kof);
        ldmx4(al[1], aLo + 16 * APAD * 2 + kof);
        #pragma unroll
        for (int p = 0; p < 4; ++p) {
            uint32_t bh[2][2], bl[2][2];
            ldmx4(&bh[0][0], bHi + p * 16 * APAD * 2 + kof);
            ldmx4(&bl[0][0], bLo + p * 16 * APAD * 2 + kof);
            #pragma unroll
            for (int tt = 0; tt < 2; ++tt)
                #pragma unroll
                for (int q = 0; q < 2; ++q) {
                    float* c = acc[tt][2 * p + q];
                    mma16816(c, ah[tt], bh[q]);
                    mma16816(c, ah[tt], bl[q]);
                    mma16816(c, al[tt], bh[q]);
                }
        }
    }

    // ---- epilogue: C frag (c0,c1)=row, (c2,c3)=row+8; cols 2*(lane&3)+{0,1} ----
    #pragma unroll
    for (int tt = 0; tt < 2; ++tt) {
        const int rbase = mbase + 16 * tt + (lane >> 2);
        #pragma unroll
        for (int h = 0; h < 2; ++h) {
            const int mi_l = rbase + 8 * h;
            if (mi_l < valid) {
                const int mi = mi0 + mi_l;
                const int r  = mi / D;
                const int i  = mi - r * D;
                float* yr = y + ((size_t)(row_begin + r) * 128) * D + i;
                #pragma unroll
                for (int nb = 0; nb < 8; ++nb) {
                    const int o = nbase + 8 * nb + 2 * (lane & 3);
                    yr[(size_t)o * D]       = acc[tt][nb][2 * h + 0];
                    yr[(size_t)(o + 1) * D] = acc[tt][nb][2 * h + 1];
                }
            }
        }
    }
}

__global__ __launch_bounds__(256)
void ilin_mma(const float* __restrict__ x0, const float* __restrict__ x1,
              const float* __restrict__ x2, const float* __restrict__ w,
              float* __restrict__ y)
{
    extern __shared__ __nv_bfloat16 sm[];
    const uint32_t smem_base = smem_u32(sm);
    const int g = blockIdx.x;
    const int z = blockIdx.y;   // 0: d1 t0 | 1..3: d3 t0..2 | 4..8: d5 t0..4

    const float* wg = w + (size_t)g * 49152;
    if (z == 0) {
        run_tile<1>(sm, smem_base, x0, wg, y, g, 0);
    } else if (z <= 3) {
        run_tile<3>(sm, smem_base, x1, wg + 16384,
                    y + (size_t)N_ROWS * 128, g, z - 1);
    } else {
        run_tile<5>(sm, smem_base, x2, wg + 32768,
                    y + (size_t)N_ROWS * 512, g, z - 4);
    }
}

extern "C" void kernel_launch(void* const* d_in, const int* in_sizes, int n_in,
                              void* d_out, int out_size)
{
    const float* x0  = (const float*)d_in[0];   // (N, 128, 1)
    const float* x1  = (const float*)d_in[1];   // (N, 128, 3)
    const float* x2  = (const float*)d_in[2];   // (N, 128, 5)
    const float* w   = (const float*)d_in[3];   // (32, 49152)
    const int*   rep = (const int*)d_in[4];     // (32,)
    float* y = (float*)d_out;

    scan_repeats<<<1, 32>>>(rep);

    cudaFuncSetAttribute(ilin_mma, cudaFuncAttributeMaxDynamicSharedMemorySize, SMEM_BYTES);
    dim3 grid(G_NUM, 9);
    ilin_mma<<<grid, 256, SMEM_BYTES>>>(x0, x1, x2, w, y);
}

// round 6
// speedup vs baseline: 2.1132x; 1.1156x over previous
#include <cuda_runtime.h>
#include <cuda_bf16.h>
#include <cstdint>

#define G_NUM   32
#define N_ROWS  2048
#define APAD2   264                    // smem row stride (bf16 elems), 528B = 33*16B -> ldmatrix conflict-free
#define A_BYTES (64 * APAD2 * 2)       // 33792
#define B_BYTES (128 * APAD2 * 2)      // 67584
#define SMEM_GEMM (A_BYTES + B_BYTES)  // 101376 -> 2 CTAs/SM
#define SMEM_CONVW (2 * 128 * 130 * 2) // 66560

__device__ int g_off2[G_NUM + 1];
__device__ __nv_bfloat16 g_wsplit[G_NUM * 3 * 128 * 256];   // [g,ir][o][hi 0:128 | lo 128:256]

__global__ void scan_repeats(const int* __restrict__ rep) {
    if (threadIdx.x == 0) {
        int s = 0;
        for (int g = 0; g < G_NUM; ++g) { g_off2[g] = s; s += rep[g]; }
        g_off2[G_NUM] = s;
    }
}

// ---------------- helpers ----------------
static __device__ __forceinline__ uint32_t smem_u32(const void* p) {
    uint32_t a;
    asm("{ .reg .u64 t; cvta.to.shared.u64 t, %1; cvt.u32.u64 %0, t; }" : "=r"(a) : "l"(p));
    return a;
}
static __device__ __forceinline__ void ldmx4(uint32_t* r, uint32_t addr) {
    asm volatile("ldmatrix.sync.aligned.m8n8.x4.shared.b16 {%0,%1,%2,%3}, [%4];"
                 : "=r"(r[0]), "=r"(r[1]), "=r"(r[2]), "=r"(r[3]) : "r"(addr));
}
static __device__ __forceinline__ void mma16816(float* c, const uint32_t* a, const uint32_t* b) {
    asm volatile(
        "mma.sync.aligned.m16n8k16.row.col.f32.bf16.bf16.f32 "
        "{%0,%1,%2,%3}, {%4,%5,%6,%7}, {%8,%9}, {%0,%1,%2,%3};"
        : "+f"(c[0]), "+f"(c[1]), "+f"(c[2]), "+f"(c[3])
        : "r"(a[0]), "r"(a[1]), "r"(a[2]), "r"(a[3]), "r"(b[0]), "r"(b[1]));
}
static __device__ __forceinline__ uint32_t pack_split(float v0, float v1, uint32_t& lo_pack) {
    __nv_bfloat16 h0 = __float2bfloat16(v0);
    __nv_bfloat16 h1 = __float2bfloat16(v1);
    __nv_bfloat16 l0 = __float2bfloat16(v0 - __bfloat162float(h0));
    __nv_bfloat16 l1 = __float2bfloat16(v1 - __bfloat162float(h1));
    __nv_bfloat162 hp(h0, h1), lp(l0, l1);
    lo_pack = *reinterpret_cast<uint32_t*>(&lp);
    return *reinterpret_cast<uint32_t*>(&hp);
}
static __device__ __forceinline__ void cpa16(uint32_t s, const void* g) {
    asm volatile("cp.async.cg.shared.global [%0], [%1], 16;" :: "r"(s), "l"(g));
}

// ---------------- W pre-conversion: fp32 [m][o] -> split bf16 [o][hi m | lo m], alpha folded ----------------
__global__ __launch_bounds__(512)
void conv_w(const float* __restrict__ w) {
    extern __shared__ __nv_bfloat16 smw[];
    __nv_bfloat16* smh = smw;
    __nv_bfloat16* sml = smw + 128 * 130;
    const int tid = threadIdx.x;
    const int g = blockIdx.x, ir = blockIdx.y;
    const float* wg = w + (size_t)g * 49152 + ir * 16384;

    for (int e = tid; e < 16384; e += 512) {       // e = m*128 + o, coalesced read
        const int m = e >> 7, o = e & 127;
        const float v = wg[e] * 0.015625f;
        const __nv_bfloat16 h = __float2bfloat16(v);
        const __nv_bfloat16 l = __float2bfloat16(v - __bfloat162float(h));
        smh[o * 130 + m] = h;                      // stride 260B -> conflict-free
        sml[o * 130 + m] = l;
    }
    __syncthreads();

    __nv_bfloat16* out = g_wsplit + ((size_t)(g * 3 + ir) << 15);
    for (int e = tid; e < 8192; e += 512) {        // u32-packed coalesced write
        const int o = e >> 6, m2 = e & 63;
        *(uint32_t*)(out + o * 256 + 2 * m2)       = *(uint32_t*)(smh + o * 130 + 2 * m2);
        *(uint32_t*)(out + o * 256 + 128 + 2 * m2) = *(uint32_t*)(sml + o * 130 + 2 * m2);
    }
}

// ---------------- GEMM tile: M64 x N128, K=128 split 3-pass ----------------
template <int D>
__device__ __forceinline__ void run_tile(char* smem, uint32_t smem_base,
                                         const float* __restrict__ x,
                                         const __nv_bfloat16* __restrict__ wsp,
                                         float* __restrict__ y,
                                         int g, int t)
{
    const int tid  = threadIdx.x;
    const int wid  = tid >> 5;
    const int lane = tid & 31;

    const int row_begin = g_off2[g];
    const int rows = g_off2[g + 1] - row_begin;
    const int Mg   = rows * D;
    const int mi0  = t * 64;
    if (mi0 >= Mg) return;
    const int valid = min(64, Mg - mi0);

    const uint32_t sA = smem_base;
    const uint32_t sB = smem_base + A_BYTES;

    // ---- B: cp.async split-bf16 rows (o-major, 512B/row) into padded smem ----
    for (int c = tid; c < 4096; c += 256) {
        const int o = c >> 5, j = c & 31;
        cpa16(sB + o * 528 + j * 16, (const char*)wsp + o * 512 + j * 16);
    }
    asm volatile("cp.async.commit_group;" ::: "memory");

    // ---- A: on-the-fly split conversion of X tile (overlapped with B loads) ----
    for (int e = tid; e < 4096; e += 256) {
        const int mi_l = e >> 6;
        const int k2   = e & 63;
        float v0 = 0.f, v1 = 0.f;
        if (mi_l < valid) {
            const int mi = mi0 + mi_l;
            const int r  = mi / D;
            const int i  = mi - r * D;
            const float* xr = x + ((size_t)(row_begin + r) * 128) * D + i;
            v0 = xr[(2 * k2) * D];
            v1 = xr[(2 * k2 + 1) * D];
        }
        uint32_t lp, hp = pack_split(v0, v1, lp);
        *(uint32_t*)(smem + mi_l * 528 + k2 * 4)       = hp;   // hi cols 0:128
        *(uint32_t*)(smem + mi_l * 528 + 256 + k2 * 4) = lp;   // lo cols 128:256
    }
    asm volatile("cp.async.wait_group 0;" ::: "memory");
    __syncthreads();

    // ---- warp tiling: 2(M) x 4(N) warps, each M32 x N32 ----
    const int mwarp = (wid >> 2) * 32;
    const int nwarp = (wid & 3) * 32;

    float acc[2][4][4];
    #pragma unroll
    for (int a = 0; a < 2; ++a)
        #pragma unroll
        for (int b = 0; b < 4; ++b)
            #pragma unroll
            for (int c = 0; c < 4; ++c) acc[a][b][c] = 0.f;

    const uint32_t aBase = sA + ((mwarp + (lane & 7) + ((lane >> 3) & 1) * 8) * APAD2 + (lane >> 4) * 8) * 2;
    const uint32_t bBase = sB + ((nwarp + (lane & 7) + ((lane >> 4) & 1) * 8) * APAD2 + ((lane >> 3) & 1) * 8) * 2;

    const int aoffs[3] = {0, 0, 256};   // byte col offsets (hi=0, lo=256B)
    const int boffs[3] = {0, 256, 0};

    #pragma unroll
    for (int p = 0; p < 3; ++p) {
        #pragma unroll
        for (int k = 0; k < 8; ++k) {
            const uint32_t co = k * 32;   // k16 step = 32B
            uint32_t a0[4], a1[4], b0[2][2], b1[2][2];
            ldmx4(a0, aBase + aoffs[p] + co);
            ldmx4(a1, aBase + 16 * 528 + aoffs[p] + co);
            ldmx4(&b0[0][0], bBase + boffs[p] + co);
            ldmx4(&b1[0][0], bBase + 16 * 528 + boffs[p] + co);
            #pragma unroll
            for (int q = 0; q < 2; ++q) {
                mma16816(acc[0][q],     a0, b0[q]);
                mma16816(acc[0][2 + q], a0, b1[q]);
                mma16816(acc[1][q],     a1, b0[q]);
                mma16816(acc[1][2 + q], a1, b1[q]);
            }
        }
    }

    // ---- epilogue: scatter to y ----
    #pragma unroll
    for (int m2 = 0; m2 < 2; ++m2) {
        const int rbase = mwarp + 16 * m2 + (lane >> 2);
        #pragma unroll
        for (int h = 0; h < 2; ++h) {
            const int mi_l = rbase + 8 * h;
            if (mi_l < valid) {
                const int mi = mi0 + mi_l;
                const int r  = mi / D;
                const int i  = mi - r * D;
                float* yr = y + ((size_t)(row_begin + r) * 128) * D + i;
                #pragma unroll
                for (int nb = 0; nb < 4; ++nb) {
                    const int o = nwarp + 8 * nb + 2 * (lane & 3);
                    yr[(size_t)o * D]       = acc[m2][nb][2 * h + 0];
                    yr[(size_t)(o + 1) * D] = acc[m2][nb][2 * h + 1];
                }
            }
        }
    }
}

__global__ __launch_bounds__(256, 2)
void ilin_mma(const float* __restrict__ x0, const float* __restrict__ x1,
              const float* __restrict__ x2, float* __restrict__ y)
{
    extern __shared__ char smem[];
    const uint32_t smem_base = smem_u32(smem);
    const int g = blockIdx.x;
    const int z = blockIdx.y;   // 0-1: d1 | 2-7: d3 | 8-17: d5

    if (z < 2) {
        run_tile<1>(smem, smem_base, x0, g_wsplit + ((size_t)(g * 3 + 0) << 15), y, g, z);
    } else if (z < 8) {
        run_tile<3>(smem, smem_base, x1, g_wsplit + ((size_t)(g * 3 + 1) << 15),
                    y + (size_t)N_ROWS * 128, g, z - 2);
    } else {
        run_tile<5>(smem, smem_base, x2, g_wsplit + ((size_t)(g * 3 + 2) << 15),
                    y + (size_t)N_ROWS * 512, g, z - 8);
    }
}

extern "C" void kernel_launch(void* const* d_in, const int* in_sizes, int n_in,
                              void* d_out, int out_size)
{
    const float* x0  = (const float*)d_in[0];   // (N, 128, 1)
    const float* x1  = (const float*)d_in[1];   // (N, 128, 3)
    const float* x2  = (const float*)d_in[2];   // (N, 128, 5)
    const float* w   = (const float*)d_in[3];   // (32, 49152)
    const int*   rep = (const int*)d_in[4];     // (32,)
    float* y = (float*)d_out;

    scan_repeats<<<1, 32>>>(rep);

    cudaFuncSetAttribute(conv_w, cudaFuncAttributeMaxDynamicSharedMemorySize, SMEM_CONVW);
    conv_w<<<dim3(G_NUM, 3), 512, SMEM_CONVW>>>(w);

    cudaFuncSetAttribute(ilin_mma, cudaFuncAttributeMaxDynamicSharedMemorySize, SMEM_GEMM);
    ilin_mma<<<dim3(G_NUM, 18), 256, SMEM_GEMM>>>(x0, x1, x2, y);
}

// round 7
// speedup vs baseline: 2.6988x; 1.2771x over previous
#include <cuda_runtime.h>
#include <cuda_bf16.h>
#include <cstdint>

#define G_NUM   32
#define N_ROWS  2048
#define STRB    272                     // smem row stride in bytes (136 bf16) -> ldmatrix conflict-free
#define SAHI    0
#define SALO    (64 * STRB)             // 17408
#define SBHI    (2 * 64 * STRB)         // 34816
#define SBLO    (SBHI + 128 * STRB)     // 69632
#define SMEM_GEMM (SBLO + 128 * STRB)   // 104448 -> 2 CTAs/SM

__global__ void dummy_unused() {}

// ---------------- helpers ----------------
static __device__ __forceinline__ uint32_t smem_u32(const void* p) {
    uint32_t a;
    asm("{ .reg .u64 t; cvta.to.shared.u64 t, %1; cvt.u32.u64 %0, t; }" : "=r"(a) : "l"(p));
    return a;
}
static __device__ __forceinline__ void ldmx4(uint32_t* r, uint32_t addr) {
    asm volatile("ldmatrix.sync.aligned.m8n8.x4.shared.b16 {%0,%1,%2,%3}, [%4];"
                 : "=r"(r[0]), "=r"(r[1]), "=r"(r[2]), "=r"(r[3]) : "r"(addr));
}
static __device__ __forceinline__ void ldmx4t(uint32_t* r, uint32_t addr) {
    asm volatile("ldmatrix.sync.aligned.m8n8.x4.trans.shared.b16 {%0,%1,%2,%3}, [%4];"
                 : "=r"(r[0]), "=r"(r[1]), "=r"(r[2]), "=r"(r[3]) : "r"(addr));
}
static __device__ __forceinline__ void mma16816(float* c, const uint32_t* a, const uint32_t* b) {
    asm volatile(
        "mma.sync.aligned.m16n8k16.row.col.f32.bf16.bf16.f32 "
        "{%0,%1,%2,%3}, {%4,%5,%6,%7}, {%8,%9}, {%0,%1,%2,%3};"
        : "+f"(c[0]), "+f"(c[1]), "+f"(c[2]), "+f"(c[3])
        : "r"(a[0]), "r"(a[1]), "r"(a[2]), "r"(a[3]), "r"(b[0]), "r"(b[1]));
}
static __device__ __forceinline__ uint32_t pack_split(float v0, float v1, uint32_t& lo_pack) {
    __nv_bfloat16 h0 = __float2bfloat16(v0);
    __nv_bfloat16 h1 = __float2bfloat16(v1);
    __nv_bfloat16 l0 = __float2bfloat16(v0 - __bfloat162float(h0));
    __nv_bfloat16 l1 = __float2bfloat16(v1 - __bfloat162float(h1));
    __nv_bfloat162 hp(h0, h1), lp(l0, l1);
    lo_pack = *reinterpret_cast<uint32_t*>(&lp);
    return *reinterpret_cast<uint32_t*>(&hp);
}

// ---------------- GEMM tile: M64 x N128, K=128, split-bf16 3-pass ----------------
// Y[mi, o] = sum_m X[mi, m] * (alpha * W[m, o]),  mi = local_row*D + i.
template <int D>
__device__ __forceinline__ void run_tile(char* smem, uint32_t smem_base,
                                         const float* __restrict__ x,
                                         const float* __restrict__ wg,
                                         const int* __restrict__ rep,
                                         float* __restrict__ y,
                                         int g, int t)
{
    const int tid  = threadIdx.x;
    const int wid  = tid >> 5;
    const int lane = tid & 31;

    // ---- warp-redundant prefix scan of repeats (no extra kernel, no sync) ----
    const int rv = rep[lane];
    int incl = rv;
    #pragma unroll
    for (int d = 1; d < 32; d <<= 1) {
        const int s = __shfl_up_sync(0xffffffffu, incl, d);
        if (lane >= d) incl += s;
    }
    const int rows      = __shfl_sync(0xffffffffu, rv, g);
    const int row_begin = __shfl_sync(0xffffffffu, incl, g) - rows;

    const int Mg  = rows * D;
    const int mi0 = t * 64;
    if (mi0 >= Mg) return;
    const int valid = min(64, Mg - mi0);

    // ---- stage B: W fp32 [m][o] -> split bf16 in NATURAL [k=m][n=o] layout ----
    #pragma unroll 4
    for (int e = tid; e < 8192; e += 256) {          // e = m*64 + o2
        const int m = e >> 6, o2 = e & 63;
        const float2 v = *(const float2*)(wg + m * 128 + 2 * o2);
        uint32_t lp, hp = pack_split(v.x * 0.015625f, v.y * 0.015625f, lp);
        *(uint32_t*)(smem + SBHI + m * STRB + o2 * 4) = hp;
        *(uint32_t*)(smem + SBLO + m * STRB + o2 * 4) = lp;
    }

    // ---- stage A: X tile -> split bf16 [mi][k] ----
    #pragma unroll 2
    for (int e = tid; e < 4096; e += 256) {          // e = mi_l*64 + k2
        const int mi_l = e >> 6;
        const int k2   = e & 63;
        float v0 = 0.f, v1 = 0.f;
        if (mi_l < valid) {
            const int mi = mi0 + mi_l;
            const int r  = mi / D;
            const int i  = mi - r * D;
            const float* xr = x + ((size_t)(row_begin + r) * 128) * D + i;
            v0 = xr[(2 * k2) * D];
            v1 = xr[(2 * k2 + 1) * D];
        }
        uint32_t lp, hp = pack_split(v0, v1, lp);
        *(uint32_t*)(smem + SAHI + mi_l * STRB + k2 * 4) = hp;
        *(uint32_t*)(smem + SALO + mi_l * STRB + k2 * 4) = lp;
    }
    __syncthreads();

    // ---- warp tiling: 2(M) x 4(N) warps, each M32 x N32 ----
    const int mwarp = (wid >> 2) * 32;
    const int nwarp = (wid & 3) * 32;

    float acc[2][4][4];
    #pragma unroll
    for (int a = 0; a < 2; ++a)
        #pragma unroll
        for (int b = 0; b < 4; ++b)
            #pragma unroll
            for (int c = 0; c < 4; ++c) acc[a][b][c] = 0.f;

    // A frag addr (row-major [m][k]): rows m, 16B col chunks
    const uint32_t aHi = smem_base + SAHI
        + (mwarp + (lane & 7) + ((lane >> 3) & 1) * 8) * STRB + (lane >> 4) * 16;
    // B frag addr (row-major [k][n], ldmatrix.trans): row = k0 + lane%16, col = n0 + (lane/16)*8
    const uint32_t bHi = smem_base + SBHI
        + (lane & 15) * STRB + (nwarp + (lane >> 4) * 8) * 2;

    #pragma unroll
    for (int k = 0; k < 8; ++k) {
        const uint32_t kofA = k * 32;          // +k16 along A cols = 32B
        const uint32_t kofB = k * 16 * STRB;   // +k16 along B rows
        uint32_t ah[2][4], al[2][4], bh[2][4], bl[2][4];
        ldmx4(ah[0], aHi + kofA);
        ldmx4(ah[1], aHi + 16 * STRB + kofA);
        ldmx4(al[0], aHi + SALO + kofA);
        ldmx4(al[1], aHi + SALO + 16 * STRB + kofA);
        ldmx4t(bh[0], bHi + kofB);             // n tiles 0,1 (n0:16)
        ldmx4t(bh[1], bHi + kofB + 32);        // n tiles 2,3 (n16:32)
        ldmx4t(bl[0], bHi + (SBLO - SBHI) + kofB);
        ldmx4t(bl[1], bHi + (SBLO - SBHI) + kofB + 32);
        #pragma unroll
        for (int m2 = 0; m2 < 2; ++m2) {
            #pragma unroll
            for (int j = 0; j < 4; ++j) {
                float* c = acc[m2][j];
                const uint32_t* bhp = &bh[j >> 1][(j & 1) * 2];
                const uint32_t* blp = &bl[j >> 1][(j & 1) * 2];
                mma16816(c, ah[m2], bhp);
                mma16816(c, ah[m2], blp);
                mma16816(c, al[m2], bhp);
            }
        }
    }

    // ---- epilogue: scatter to y ----
    #pragma unroll
    for (int m2 = 0; m2 < 2; ++m2) {
        const int rbase = mwarp + 16 * m2 + (lane >> 2);
        #pragma unroll
        for (int h = 0; h < 2; ++h) {
            const int mi_l = rbase + 8 * h;
            if (mi_l < valid) {
                const int mi = mi0 + mi_l;
                const int r  = mi / D;
                const int i  = mi - r * D;
                float* yr = y + ((size_t)(row_begin + r) * 128) * D + i;
                #pragma unroll
                for (int nb = 0; nb < 4; ++nb) {
                    const int o = nwarp + 8 * nb + 2 * (lane & 3);
                    yr[(size_t)o * D]       = acc[m2][nb][2 * h + 0];
                    yr[(size_t)(o + 1) * D] = acc[m2][nb][2 * h + 1];
                }
            }
        }
    }
}

__global__ __launch_bounds__(256, 2)
void ilin_mma(const float* __restrict__ x0, const float* __restrict__ x1,
              const float* __restrict__ x2, const float* __restrict__ w,
              const int* __restrict__ rep, float* __restrict__ y)
{
    extern __shared__ char smem[];
    const uint32_t smem_base = smem_u32(smem);
    const int g = blockIdx.x;
    const int z = blockIdx.y;   // 0-1: d1 | 2-7: d3 | 8-17: d5

    const float* wg = w + (size_t)g * 49152;
    if (z < 2) {
        run_tile<1>(smem, smem_base, x0, wg, rep, y, g, z);
    } else if (z < 8) {
        run_tile<3>(smem, smem_base, x1, wg + 16384, rep,
                    y + (size_t)N_ROWS * 128, g, z - 2);
    } else {
        run_tile<5>(smem, smem_base, x2, wg + 32768, rep,
                    y + (size_t)N_ROWS * 512, g, z - 8);
    }
}

extern "C" void kernel_launch(void* const* d_in, const int* in_sizes, int n_in,
                              void* d_out, int out_size)
{
    const float* x0  = (const float*)d_in[0];   // (N, 128, 1)
    const float* x1  = (const float*)d_in[1];   // (N, 128, 3)
    const float* x2  = (const float*)d_in[2];   // (N, 128, 5)
    const float* w   = (const float*)d_in[3];   // (32, 49152)
    const int*   rep = (const int*)d_in[4];     // (32,)
    float* y = (float*)d_out;

    cudaFuncSetAttribute(ilin_mma, cudaFuncAttributeMaxDynamicSharedMemorySize, SMEM_GEMM);
    ilin_mma<<<dim3(G_NUM, 18), 256, SMEM_GEMM>>>(x0, x1, x2, w, rep, y);
}